// round 13
// baseline (speedup 1.0000x reference)
#include <cuda_runtime.h>
#include <cuda_bf16.h>
#include <cstdint>

#define MB 8192   // M
#define KD 1024   // K
#define ND 4096   // N

// ---------------- device scratch (no allocs allowed) ----------------
__device__ float g_xsq[MB];
__device__ float g_wsq[ND];
__device__ float g_wsq_part[4][ND];
__device__ __nv_bfloat16 g_xb[(size_t)MB * KD];   // x in bf16, [M][K]
__device__ __nv_bfloat16 g_wb[(size_t)ND * KD];   // W in bf16, TRANSPOSED [N][K]

// ---------------- helpers ----------------
__device__ __forceinline__ uint32_t smem_u32(const void* p) {
    uint32_t a;
    asm("{ .reg .u64 t; cvta.to.shared.u64 t, %1; cvt.u32.u64 %0, t; }"
        : "=r"(a) : "l"(p));
    return a;
}

__device__ __forceinline__ void cp_async16(uint32_t dst, const void* src) {
    asm volatile("cp.async.cg.shared.global [%0], [%1], 16;"
                 :: "r"(dst), "l"(src) : "memory");
}

__device__ __forceinline__ uint32_t swz(uint32_t b) {  // SW128: Swizzle<3,4,3>
    return b ^ ((b >> 3) & 0x70);
}

__device__ __forceinline__ void ldsm_x4(uint32_t* r, uint32_t addr) {
    asm volatile("ldmatrix.sync.aligned.m8n8.x4.shared.b16 {%0,%1,%2,%3}, [%4];"
                 : "=r"(r[0]), "=r"(r[1]), "=r"(r[2]), "=r"(r[3]) : "r"(addr));
}

__device__ __forceinline__ void mma16816(float* d, const uint32_t* a,
                                         uint32_t b0, uint32_t b1) {
    asm volatile(
        "mma.sync.aligned.m16n8k16.row.col.f32.bf16.bf16.f32 "
        "{%0,%1,%2,%3}, {%4,%5,%6,%7}, {%8,%9}, {%0,%1,%2,%3};"
        : "+f"(d[0]), "+f"(d[1]), "+f"(d[2]), "+f"(d[3])
        : "r"(a[0]), "r"(a[1]), "r"(a[2]), "r"(a[3]), "r"(b0), "r"(b1));
}

// ---------------------------------------------------------------------------
// convert x -> bf16 and compute ||x_b||^2 (one warp per row)
// ---------------------------------------------------------------------------
__global__ void convert_x_kernel(const float* __restrict__ x) {
    int row  = blockIdx.x * 8 + (threadIdx.x >> 5);
    int lane = threadIdx.x & 31;
    const float4* xr = reinterpret_cast<const float4*>(x + (size_t)row * KD);
    uint2* dst = reinterpret_cast<uint2*>(g_xb + (size_t)row * KD);
    float s = 0.f;
    #pragma unroll 8
    for (int i = lane; i < KD / 4; i += 32) {
        float4 v = xr[i];
        s += v.x * v.x + v.y * v.y + v.z * v.z + v.w * v.w;
        __nv_bfloat162 lo = __floats2bfloat162_rn(v.x, v.y);
        __nv_bfloat162 hi = __floats2bfloat162_rn(v.z, v.w);
        uint2 u;
        u.x = *reinterpret_cast<uint32_t*>(&lo);
        u.y = *reinterpret_cast<uint32_t*>(&hi);
        dst[i] = u;
    }
    #pragma unroll
    for (int o = 16; o > 0; o >>= 1) s += __shfl_xor_sync(0xffffffffu, s, o);
    if (lane == 0) g_xsq[row] = s;
}

// ---------------------------------------------------------------------------
// convert W [K][N] -> bf16 transposed g_wb [N][K] + partial wsq.
// grid (ND/32, 4): blockIdx.y owns an independent 256-row K slab.
// ---------------------------------------------------------------------------
__global__ void convert_w_fused(const float* __restrict__ w) {
    __shared__ __nv_bfloat16 t[64][34];
    __shared__ float red[8][32];
    const int n0    = blockIdx.x * 32;
    const int kbase = blockIdx.y * 256;
    const int tid = threadIdx.x;
    const int c   = tid & 31, r0 = tid >> 5;
    const int n   = tid >> 3, seg = (tid & 7) * 8;

    float sq = 0.f;
    for (int k0 = kbase; k0 < kbase + 256; k0 += 64) {
        #pragma unroll
        for (int p = 0; p < 8; ++p) {
            int r = p * 8 + r0;
            float v = w[(size_t)(k0 + r) * ND + n0 + c];
            sq += v * v;
            t[r][c] = __float2bfloat16_rn(v);
        }
        __syncthreads();
        __nv_bfloat16 tmp[8];
        #pragma unroll
        for (int i = 0; i < 8; ++i) tmp[i] = t[seg + i][n];
        *reinterpret_cast<uint4*>(g_wb + (size_t)(n0 + n) * KD + k0 + seg) =
            *reinterpret_cast<uint4*>(tmp);
        __syncthreads();
    }
    red[r0][c] = sq;
    __syncthreads();
    if (tid < 32) {
        float s = 0.f;
        #pragma unroll
        for (int p = 0; p < 8; ++p) s += red[p][tid];
        g_wsq_part[blockIdx.y][n0 + tid] = s;
    }
}

__global__ void wsq_reduce_kernel() {
    int i = blockIdx.x * 256 + threadIdx.x;
    g_wsq[i] = (g_wsq_part[0][i] + g_wsq_part[1][i]) +
               (g_wsq_part[2][i] + g_wsq_part[3][i]);
}

// ---------------------------------------------------------------------------
// mma.sync bf16 GEMM + fused epilogue (R8 layout + issue-slot diet):
//   C[m,n] = xsq[m] + wsq[n] - 2 * (x @ W)[m,n]
// 128x128 CTA tile, 8 warps x (64x32), KC=64, 3-stage cp.async ring,
// 1 barrier/chunk, 2 CTAs/SM. All cp.async/ldmatrix addresses are
// precomputed/advanced-by-constant; ks enters only as a LOP3 immediate.
// ---------------------------------------------------------------------------
#define KC 64
#define NCH (KD / KC)          // 16
#define STGB 16384             // bytes per operand per stage
#define SMEM_BYTES (6 * STGB)  // 96 KB -> 2 CTAs/SM

__global__ __launch_bounds__(256, 2)
void rbf_mma_gemm(float* __restrict__ C) {
    extern __shared__ __align__(1024) char smem[];
    const uint32_t sb = smem_u32(smem);

    const int tid  = threadIdx.x;
    const int lane = tid & 31;
    const int wid  = tid >> 5;
    const int wm   = (wid & 1) * 64;
    const int wn   = (wid >> 1) * 32;
    const int rowBase = blockIdx.y * 128;
    const int colBase = blockIdx.x * 128;

    // ---- cp.async: precomputed smem offsets + running global pointers ----
    const int lr  = tid >> 3;          // 0..31
    const int seg = (tid & 7) * 16;    // byte 0..112
    uint32_t smoff[4];                 // identical geometry for A and B
    #pragma unroll
    for (int p = 0; p < 4; ++p)
        smoff[p] = swz((uint32_t)(p * 32 + lr) * 128 + seg);

    const char* gA = (const char*)(g_xb + (size_t)(rowBase + lr) * KD) + seg;
    const char* gB = (const char*)(g_wb + (size_t)(colBase + lr) * KD) + seg;
    // row stride between p slots: 32 rows * 128 B = 4096... (32*KD*2 = 65536 B)

    auto load_chunk = [&](uint32_t stA, uint32_t stB,
                          const char* srcA, const char* srcB) {
        #pragma unroll
        for (int p = 0; p < 4; ++p) {
            cp_async16(stA + smoff[p], srcA + (size_t)p * (32 * KD * 2));
            cp_async16(stB + smoff[p], srcB + (size_t)p * (32 * KD * 2));
        }
        asm volatile("cp.async.commit_group;" ::: "memory");
    };

    // ---- ldmatrix: per-warp swizzled offsets; stage base added per chunk,
    //      ks folded as XOR immediate (stage bases 1024-aligned; XOR hits
    //      bits 5-6 only, so aT + (off ^ imm) == (aT + off) ^ imm) ----
    const int rl = lane & 15;
    const int hi = (lane >> 4) * 16;
    uint32_t offA[4], offB[2];
    #pragma unroll
    for (int mt = 0; mt < 4; ++mt)
        offA[mt] = swz((uint32_t)(wm + mt * 16 + rl) * 128 + hi);
    #pragma unroll
    for (int nt = 0; nt < 2; ++nt)
        offB[nt] = swz((uint32_t)(wn + nt * 16 + rl) * 128 + hi);

    float acc[4][4][4];
    #pragma unroll
    for (int i = 0; i < 4; ++i)
        #pragma unroll
        for (int j = 0; j < 4; ++j)
            #pragma unroll
            for (int k = 0; k < 4; ++k) acc[i][j][k] = 0.f;

    load_chunk(sb, sb + 3 * STGB, gA, gB);
    gA += 128; gB += 128;
    load_chunk(sb + STGB, sb + 4 * STGB, gA, gB);
    gA += 128; gB += 128;

    int s = 0;
    for (int c = 0; c < NCH; ++c) {
        asm volatile("cp.async.wait_group 1;" ::: "memory");
        __syncthreads();   // stage s ready; all warps done with stage (s+2)%3

        if (c + 2 < NCH) {
            const uint32_t s2 = (s + 2 >= 3) ? (uint32_t)(s - 1) : (uint32_t)(s + 2);
            load_chunk(sb + s2 * STGB, sb + (3 + s2) * STGB, gA, gB);
            gA += 128; gB += 128;
        }

        const uint32_t aT = sb + (uint32_t)s * STGB;
        const uint32_t bT = sb + 3 * STGB + (uint32_t)s * STGB;
        uint32_t aAddr[4], bAddr[2];
        #pragma unroll
        for (int mt = 0; mt < 4; ++mt) aAddr[mt] = aT + offA[mt];
        #pragma unroll
        for (int nt = 0; nt < 2; ++nt) bAddr[nt] = bT + offB[nt];

        #pragma unroll
        for (int ks = 0; ks < 4; ++ks) {
            uint32_t a[4][4], bq[2][4];
            #pragma unroll
            for (int mt = 0; mt < 4; ++mt)
                ldsm_x4(a[mt], aAddr[mt] ^ (ks << 5));
            #pragma unroll
            for (int nt = 0; nt < 2; ++nt)
                ldsm_x4(bq[nt], bAddr[nt] ^ (ks << 5));
            #pragma unroll
            for (int mt = 0; mt < 4; ++mt) {
                #pragma unroll
                for (int nt = 0; nt < 2; ++nt) {
                    mma16816(acc[mt][nt * 2 + 0], a[mt], bq[nt][0], bq[nt][2]);
                    mma16816(acc[mt][nt * 2 + 1], a[mt], bq[nt][1], bq[nt][3]);
                }
            }
        }
        s = (s == 2) ? 0 : s + 1;
    }

    // Epilogue: lane l -> row g=l>>2 (+8), cols 2*(l&3) within each n8 frag
    const int g  = lane >> 2;
    const int tg = (lane & 3) * 2;
    #pragma unroll
    for (int mt = 0; mt < 4; ++mt) {
        const int r0 = rowBase + wm + mt * 16 + g;
        const float xs0 = g_xsq[r0];
        const float xs1 = g_xsq[r0 + 8];
        float* p0 = C + (size_t)r0 * ND + colBase + wn;
        float* p1 = p0 + (size_t)8 * ND;
        #pragma unroll
        for (int nf = 0; nf < 4; ++nf) {
            const int col = nf * 8 + tg;
            const float w0 = g_wsq[colBase + wn + col];
            const float w1 = g_wsq[colBase + wn + col + 1];
            float2 v0, v1;
            v0.x = xs0 + w0 - 2.f * acc[mt][nf][0];
            v0.y = xs0 + w1 - 2.f * acc[mt][nf][1];
            v1.x = xs1 + w0 - 2.f * acc[mt][nf][2];
            v1.y = xs1 + w1 - 2.f * acc[mt][nf][3];
            *reinterpret_cast<float2*>(p0 + col) = v0;
            *reinterpret_cast<float2*>(p1 + col) = v1;
        }
    }
}

// ---------------------------------------------------------------------------
extern "C" void kernel_launch(void* const* d_in, const int* in_sizes, int n_in,
                              void* d_out, int out_size) {
    const float* x = (const float*)d_in[0];
    const float* w = (const float*)d_in[1];
    float* out = (float*)d_out;

    convert_x_kernel<<<MB / 8, 256>>>(x);
    convert_w_fused<<<dim3(ND / 32, 4), 256>>>(w);
    wsq_reduce_kernel<<<ND / 256, 256>>>();

    cudaFuncSetAttribute(rbf_mma_gemm,
                         cudaFuncAttributeMaxDynamicSharedMemorySize, SMEM_BYTES);
    rbf_mma_gemm<<<dim3(ND / 128, MB / 128), 256, SMEM_BYTES>>>(out);
}

// round 14
// speedup vs baseline: 1.5154x; 1.5154x over previous
#include <cuda_runtime.h>
#include <cuda_bf16.h>
#include <cstdint>

#define MB 8192   // M
#define KD 1024   // K
#define ND 4096   // N

// ---------------- device scratch (no allocs allowed) ----------------
__device__ float g_xsq[MB];
__device__ float g_wsq[ND];
__device__ float g_wsq_part[4][ND];
__device__ __nv_bfloat16 g_xb[(size_t)MB * KD];   // x in bf16, [M][K]
__device__ __nv_bfloat16 g_wb[(size_t)ND * KD];   // W in bf16, TRANSPOSED [N][K]

// ---------------- helpers ----------------
__device__ __forceinline__ uint32_t smem_u32(const void* p) {
    uint32_t a;
    asm("{ .reg .u64 t; cvta.to.shared.u64 t, %1; cvt.u32.u64 %0, t; }"
        : "=r"(a) : "l"(p));
    return a;
}

__device__ __forceinline__ void cp_async16(uint32_t dst, const void* src) {
    asm volatile("cp.async.cg.shared.global [%0], [%1], 16;"
                 :: "r"(dst), "l"(src) : "memory");
}

__device__ __forceinline__ uint32_t swz(uint32_t b) {  // SW128: Swizzle<3,4,3>
    return b ^ ((b >> 3) & 0x70);
}

__device__ __forceinline__ void ldsm_x4(uint32_t* r, uint32_t addr) {
    asm volatile("ldmatrix.sync.aligned.m8n8.x4.shared.b16 {%0,%1,%2,%3}, [%4];"
                 : "=r"(r[0]), "=r"(r[1]), "=r"(r[2]), "=r"(r[3]) : "r"(addr));
}

__device__ __forceinline__ void mma16816(float* d, const uint32_t* a,
                                         uint32_t b0, uint32_t b1) {
    asm volatile(
        "mma.sync.aligned.m16n8k16.row.col.f32.bf16.bf16.f32 "
        "{%0,%1,%2,%3}, {%4,%5,%6,%7}, {%8,%9}, {%0,%1,%2,%3};"
        : "+f"(d[0]), "+f"(d[1]), "+f"(d[2]), "+f"(d[3])
        : "r"(a[0]), "r"(a[1]), "r"(a[2]), "r"(a[3]), "r"(b0), "r"(b1));
}

// ---------------------------------------------------------------------------
// convert x -> bf16 and compute ||x_b||^2 (one warp per row)
// ---------------------------------------------------------------------------
__global__ void convert_x_kernel(const float* __restrict__ x) {
    int row  = blockIdx.x * 8 + (threadIdx.x >> 5);
    int lane = threadIdx.x & 31;
    const float4* xr = reinterpret_cast<const float4*>(x + (size_t)row * KD);
    uint2* dst = reinterpret_cast<uint2*>(g_xb + (size_t)row * KD);
    float s = 0.f;
    #pragma unroll 8
    for (int i = lane; i < KD / 4; i += 32) {
        float4 v = xr[i];
        s += v.x * v.x + v.y * v.y + v.z * v.z + v.w * v.w;
        __nv_bfloat162 lo = __floats2bfloat162_rn(v.x, v.y);
        __nv_bfloat162 hi = __floats2bfloat162_rn(v.z, v.w);
        uint2 u;
        u.x = *reinterpret_cast<uint32_t*>(&lo);
        u.y = *reinterpret_cast<uint32_t*>(&hi);
        dst[i] = u;
    }
    #pragma unroll
    for (int o = 16; o > 0; o >>= 1) s += __shfl_xor_sync(0xffffffffu, s, o);
    if (lane == 0) g_xsq[row] = s;
}

// ---------------------------------------------------------------------------
// convert W [K][N] -> bf16 transposed g_wb [N][K] + partial wsq.
// grid (ND/32, 4): blockIdx.y owns an independent 256-row K slab.
// ---------------------------------------------------------------------------
__global__ void convert_w_fused(const float* __restrict__ w) {
    __shared__ __nv_bfloat16 t[64][34];
    __shared__ float red[8][32];
    const int n0    = blockIdx.x * 32;
    const int kbase = blockIdx.y * 256;
    const int tid = threadIdx.x;
    const int c   = tid & 31, r0 = tid >> 5;
    const int n   = tid >> 3, seg = (tid & 7) * 8;

    float sq = 0.f;
    for (int k0 = kbase; k0 < kbase + 256; k0 += 64) {
        #pragma unroll
        for (int p = 0; p < 8; ++p) {
            int r = p * 8 + r0;
            float v = w[(size_t)(k0 + r) * ND + n0 + c];
            sq += v * v;
            t[r][c] = __float2bfloat16_rn(v);
        }
        __syncthreads();
        __nv_bfloat16 tmp[8];
        #pragma unroll
        for (int i = 0; i < 8; ++i) tmp[i] = t[seg + i][n];
        *reinterpret_cast<uint4*>(g_wb + (size_t)(n0 + n) * KD + k0 + seg) =
            *reinterpret_cast<uint4*>(tmp);
        __syncthreads();
    }
    red[r0][c] = sq;
    __syncthreads();
    if (tid < 32) {
        float s = 0.f;
        #pragma unroll
        for (int p = 0; p < 8; ++p) s += red[p][tid];
        g_wsq_part[blockIdx.y][n0 + tid] = s;
    }
}

__global__ void wsq_reduce_kernel() {
    int i = blockIdx.x * 256 + threadIdx.x;
    g_wsq[i] = (g_wsq_part[0][i] + g_wsq_part[1][i]) +
               (g_wsq_part[2][i] + g_wsq_part[3][i]);
}

// ---------------------------------------------------------------------------
// mma.sync bf16 GEMM + fused epilogue  (EXACT R8 mainloop — proven 188.8us):
//   C[m,n] = xsq[m] + wsq[n] - 2 * (x @ W)[m,n]
// 128x128 CTA tile, K-chunks of 64, 3-stage cp.async pipeline (one barrier
// per chunk), 8 warps, 64x32 warp tile, m16n8k16 HMMA f32 accum,
// XOR-based ldmatrix addressing (SW128 mask invariant in ks).
// ---------------------------------------------------------------------------
#define KC 64
#define NCH (KD / KC)          // 16
#define STGB 16384             // bytes per operand per stage
#define SMEM_BYTES (6 * STGB)  // 96 KB

__global__ __launch_bounds__(256, 2)
void rbf_mma_gemm(float* __restrict__ C) {
    extern __shared__ __align__(1024) char smem[];
    const uint32_t sb = smem_u32(smem);
    // stage s: A at sb + s*16K, B at sb + 48K + s*16K

    const int tid  = threadIdx.x;
    const int lane = tid & 31;
    const int wid  = tid >> 5;
    const int wm   = (wid & 1) * 64;    // warp M offset
    const int wn   = (wid >> 1) * 32;   // warp N offset
    const int rowBase = blockIdx.y * 128;
    const int colBase = blockIdx.x * 128;

    // cp.async geometry: 256 threads x 4 rows x 16B per operand tile
    const int lr  = tid >> 3;          // 0..31
    const int seg = (tid & 7) * 16;    // byte 0..112

    auto load_chunk = [&](int c, int s) {
        const uint32_t aT = sb + (uint32_t)s * STGB;
        const uint32_t bT = sb + 3 * STGB + (uint32_t)s * STGB;
        const size_t k0 = (size_t)c * KC;
        #pragma unroll
        for (int p = 0; p < 4; ++p) {
            int r = p * 32 + lr;
            cp_async16(aT + swz(r * 128 + seg),
                       (const char*)(g_xb + (size_t)(rowBase + r) * KD + k0) + seg);
            cp_async16(bT + swz(r * 128 + seg),
                       (const char*)(g_wb + (size_t)(colBase + r) * KD + k0) + seg);
        }
        asm volatile("cp.async.commit_group;" ::: "memory");
    };

    // ldmatrix base offsets (swizzled once; ks advances via XOR of ks*32,
    // valid because the SW128 mask depends only on bits 7-9 = row bits)
    const int rl = lane & 15;
    const int hi = (lane >> 4) * 16;
    uint32_t offA[4], offB[2];
    #pragma unroll
    for (int mt = 0; mt < 4; ++mt)
        offA[mt] = swz((uint32_t)(wm + mt * 16 + rl) * 128 + hi);
    #pragma unroll
    for (int nt = 0; nt < 2; ++nt)
        offB[nt] = swz((uint32_t)(wn + nt * 16 + rl) * 128 + hi);

    float acc[4][4][4];
    #pragma unroll
    for (int i = 0; i < 4; ++i)
        #pragma unroll
        for (int j = 0; j < 4; ++j)
            #pragma unroll
            for (int k = 0; k < 4; ++k) acc[i][j][k] = 0.f;

    load_chunk(0, 0);
    load_chunk(1, 1);

    int s = 0, s2 = 2;   // stage of chunk c, stage for chunk c+2
    for (int c = 0; c < NCH; ++c) {
        asm volatile("cp.async.wait_group 1;" ::: "memory");
        __syncthreads();   // also guarantees all warps done computing c-1

        const uint32_t aT = sb + (uint32_t)s * STGB;
        const uint32_t bT = sb + 3 * STGB + (uint32_t)s * STGB;

        #pragma unroll
        for (int ks = 0; ks < 4; ++ks) {
            uint32_t a[4][4], bq[2][4];
            #pragma unroll
            for (int mt = 0; mt < 4; ++mt)
                ldsm_x4(a[mt], aT + (offA[mt] ^ (ks << 5)));
            #pragma unroll
            for (int nt = 0; nt < 2; ++nt)
                ldsm_x4(bq[nt], bT + (offB[nt] ^ (ks << 5)));
            #pragma unroll
            for (int mt = 0; mt < 4; ++mt) {
                #pragma unroll
                for (int nt = 0; nt < 2; ++nt) {
                    mma16816(acc[mt][nt * 2 + 0], a[mt], bq[nt][0], bq[nt][2]);
                    mma16816(acc[mt][nt * 2 + 1], a[mt], bq[nt][1], bq[nt][3]);
                }
            }
        }

        if (c + 2 < NCH) load_chunk(c + 2, s2);
        s  = (s  == 2) ? 0 : s + 1;
        s2 = (s2 == 2) ? 0 : s2 + 1;
    }

    // Epilogue: lane l -> row g=l>>2 (+8), cols 2*(l&3) within each n8 frag
    const int g  = lane >> 2;
    const int tg = (lane & 3) * 2;
    #pragma unroll
    for (int mt = 0; mt < 4; ++mt) {
        const int r0 = rowBase + wm + mt * 16 + g;
        const float xs0 = g_xsq[r0];
        const float xs1 = g_xsq[r0 + 8];
        float* p0 = C + (size_t)r0 * ND + colBase + wn;
        float* p1 = p0 + (size_t)8 * ND;
        #pragma unroll
        for (int nf = 0; nf < 4; ++nf) {
            const int col = nf * 8 + tg;
            const float w0 = g_wsq[colBase + wn + col];
            const float w1 = g_wsq[colBase + wn + col + 1];
            float2 v0, v1;
            v0.x = xs0 + w0 - 2.f * acc[mt][nf][0];
            v0.y = xs0 + w1 - 2.f * acc[mt][nf][1];
            v1.x = xs1 + w0 - 2.f * acc[mt][nf][2];
            v1.y = xs1 + w1 - 2.f * acc[mt][nf][3];
            *reinterpret_cast<float2*>(p0 + col) = v0;
            *reinterpret_cast<float2*>(p1 + col) = v1;
        }
    }
}

// ---------------------------------------------------------------------------
extern "C" void kernel_launch(void* const* d_in, const int* in_sizes, int n_in,
                              void* d_out, int out_size) {
    const float* x = (const float*)d_in[0];
    const float* w = (const float*)d_in[1];
    float* out = (float*)d_out;

    convert_x_kernel<<<MB / 8, 256>>>(x);
    convert_w_fused<<<dim3(ND / 32, 4), 256>>>(w);
    wsq_reduce_kernel<<<ND / 256, 256>>>();

    cudaFuncSetAttribute(rbf_mma_gemm,
                         cudaFuncAttributeMaxDynamicSharedMemorySize, SMEM_BYTES);
    rbf_mma_gemm<<<dim3(ND / 128, MB / 128), 256, SMEM_BYTES>>>(out);
}

// round 15
// speedup vs baseline: 1.5588x; 1.0287x over previous
#include <cuda_runtime.h>
#include <cuda_bf16.h>
#include <cstdint>

#define MB 8192   // M
#define KD 1024   // K
#define ND 4096   // N

// ---------------- device scratch (no allocs allowed) ----------------
__device__ float g_xsq[MB];
__device__ float g_wsq_part[4][ND];
__device__ __nv_bfloat16 g_xb[(size_t)MB * KD];   // x in bf16, [M][K]
__device__ __nv_bfloat16 g_wb[(size_t)ND * KD];   // W in bf16, TRANSPOSED [N][K]

// ---------------- helpers ----------------
__device__ __forceinline__ uint32_t smem_u32(const void* p) {
    uint32_t a;
    asm("{ .reg .u64 t; cvta.to.shared.u64 t, %1; cvt.u32.u64 %0, t; }"
        : "=r"(a) : "l"(p));
    return a;
}

__device__ __forceinline__ void cp_async16(uint32_t dst, const void* src) {
    asm volatile("cp.async.cg.shared.global [%0], [%1], 16;"
                 :: "r"(dst), "l"(src) : "memory");
}

__device__ __forceinline__ uint32_t swz(uint32_t b) {  // SW128: Swizzle<3,4,3>
    return b ^ ((b >> 3) & 0x70);
}

__device__ __forceinline__ void ldsm_x4(uint32_t* r, uint32_t addr) {
    asm volatile("ldmatrix.sync.aligned.m8n8.x4.shared.b16 {%0,%1,%2,%3}, [%4];"
                 : "=r"(r[0]), "=r"(r[1]), "=r"(r[2]), "=r"(r[3]) : "r"(addr));
}

__device__ __forceinline__ void mma16816(float* d, const uint32_t* a,
                                         uint32_t b0, uint32_t b1) {
    asm volatile(
        "mma.sync.aligned.m16n8k16.row.col.f32.bf16.bf16.f32 "
        "{%0,%1,%2,%3}, {%4,%5,%6,%7}, {%8,%9}, {%0,%1,%2,%3};"
        : "+f"(d[0]), "+f"(d[1]), "+f"(d[2]), "+f"(d[3])
        : "r"(a[0]), "r"(a[1]), "r"(a[2]), "r"(a[3]), "r"(b0), "r"(b1));
}

// ---------------------------------------------------------------------------
// Merged prep kernel, 256 threads/block:
//   blocks [0, 1024):     convert x rows -> bf16 + ||x_b||^2
//   blocks [1024, 1536):  convert W stripe -> transposed bf16 + partial wsq
// Each block takes exactly one branch, so barriers stay block-uniform.
// ---------------------------------------------------------------------------
__global__ void prep_kernel(const float* __restrict__ x,
                            const float* __restrict__ w) {
    const int tid = threadIdx.x;
    if (blockIdx.x < 1024) {
        // ---- convert_x: 8 rows per block, one warp per row ----
        int row  = blockIdx.x * 8 + (tid >> 5);
        int lane = tid & 31;
        const float4* xr = reinterpret_cast<const float4*>(x + (size_t)row * KD);
        uint2* dst = reinterpret_cast<uint2*>(g_xb + (size_t)row * KD);
        float s = 0.f;
        #pragma unroll 8
        for (int i = lane; i < KD / 4; i += 32) {
            float4 v = xr[i];
            s += v.x * v.x + v.y * v.y + v.z * v.z + v.w * v.w;
            __nv_bfloat162 lo = __floats2bfloat162_rn(v.x, v.y);
            __nv_bfloat162 hi = __floats2bfloat162_rn(v.z, v.w);
            uint2 u;
            u.x = *reinterpret_cast<uint32_t*>(&lo);
            u.y = *reinterpret_cast<uint32_t*>(&hi);
            dst[i] = u;
        }
        #pragma unroll
        for (int o = 16; o > 0; o >>= 1) s += __shfl_xor_sync(0xffffffffu, s, o);
        if (lane == 0) g_xsq[row] = s;
    } else {
        // ---- convert_w: 32-col stripe over a 256-row K slab ----
        __shared__ __nv_bfloat16 t[64][34];
        __shared__ float red[8][32];
        const int bid   = blockIdx.x - 1024;
        const int n0    = (bid & 127) * 32;     // ND/32 = 128 stripes
        const int kbase = (bid >> 7) * 256;     // 4 K slabs
        const int c   = tid & 31, r0 = tid >> 5;
        const int n   = tid >> 3, seg = (tid & 7) * 8;

        float sq = 0.f;
        for (int k0 = kbase; k0 < kbase + 256; k0 += 64) {
            #pragma unroll
            for (int p = 0; p < 8; ++p) {
                int r = p * 8 + r0;
                float v = w[(size_t)(k0 + r) * ND + n0 + c];
                sq += v * v;
                t[r][c] = __float2bfloat16_rn(v);
            }
            __syncthreads();
            __nv_bfloat16 tmp[8];
            #pragma unroll
            for (int i = 0; i < 8; ++i) tmp[i] = t[seg + i][n];
            *reinterpret_cast<uint4*>(g_wb + (size_t)(n0 + n) * KD + k0 + seg) =
                *reinterpret_cast<uint4*>(tmp);
            __syncthreads();
        }
        red[r0][c] = sq;
        __syncthreads();
        if (tid < 32) {
            float s = 0.f;
            #pragma unroll
            for (int p = 0; p < 8; ++p) s += red[p][tid];
            g_wsq_part[bid >> 7][n0 + tid] = s;
        }
    }
}

// ---------------------------------------------------------------------------
// mma.sync bf16 GEMM + fused epilogue  (R8 mainloop — proven 188.8us):
//   C[m,n] = xsq[m] + wsq[n] - 2 * (x @ W)[m,n]
// wsq partials are summed into a 512B smem stage before the mainloop
// (made visible to the epilogue by the mainloop barriers).
// ---------------------------------------------------------------------------
#define KC 64
#define NCH (KD / KC)          // 16
#define STGB 16384             // bytes per operand per stage
#define SMEM_BYTES (6 * STGB + 512)  // 96 KB tiles + wsq stage

__global__ __launch_bounds__(256, 2)
void rbf_mma_gemm(float* __restrict__ C) {
    extern __shared__ __align__(1024) char smem[];
    const uint32_t sb = smem_u32(smem);
    float* wsq_s = reinterpret_cast<float*>(smem + 6 * STGB);

    const int tid  = threadIdx.x;
    const int lane = tid & 31;
    const int wid  = tid >> 5;
    const int wm   = (wid & 1) * 64;    // warp M offset
    const int wn   = (wid >> 1) * 32;   // warp N offset
    const int rowBase = blockIdx.y * 128;
    const int colBase = blockIdx.x * 128;

    // cp.async geometry: 256 threads x 4 rows x 16B per operand tile
    const int lr  = tid >> 3;          // 0..31
    const int seg = (tid & 7) * 16;    // byte 0..112

    auto load_chunk = [&](int c, int s) {
        const uint32_t aT = sb + (uint32_t)s * STGB;
        const uint32_t bT = sb + 3 * STGB + (uint32_t)s * STGB;
        const size_t k0 = (size_t)c * KC;
        #pragma unroll
        for (int p = 0; p < 4; ++p) {
            int r = p * 32 + lr;
            cp_async16(aT + swz(r * 128 + seg),
                       (const char*)(g_xb + (size_t)(rowBase + r) * KD + k0) + seg);
            cp_async16(bT + swz(r * 128 + seg),
                       (const char*)(g_wb + (size_t)(colBase + r) * KD + k0) + seg);
        }
        asm volatile("cp.async.commit_group;" ::: "memory");
    };

    load_chunk(0, 0);
    load_chunk(1, 1);

    // Fold wsq partial reduction into this kernel (replaces reduce launch).
    // Visible to the epilogue via the mainloop __syncthreads.
    if (tid < 128) {
        int col = colBase + tid;
        wsq_s[tid] = (g_wsq_part[0][col] + g_wsq_part[1][col]) +
                     (g_wsq_part[2][col] + g_wsq_part[3][col]);
    }

    // ldmatrix base offsets (swizzled once; ks advances via XOR of ks*32,
    // valid because the SW128 mask depends only on bits 7-9 = row bits)
    const int rl = lane & 15;
    const int hi = (lane >> 4) * 16;
    uint32_t offA[4], offB[2];
    #pragma unroll
    for (int mt = 0; mt < 4; ++mt)
        offA[mt] = swz((uint32_t)(wm + mt * 16 + rl) * 128 + hi);
    #pragma unroll
    for (int nt = 0; nt < 2; ++nt)
        offB[nt] = swz((uint32_t)(wn + nt * 16 + rl) * 128 + hi);

    float acc[4][4][4];
    #pragma unroll
    for (int i = 0; i < 4; ++i)
        #pragma unroll
        for (int j = 0; j < 4; ++j)
            #pragma unroll
            for (int k = 0; k < 4; ++k) acc[i][j][k] = 0.f;

    int s = 0, s2 = 2;   // stage of chunk c, stage for chunk c+2
    for (int c = 0; c < NCH; ++c) {
        asm volatile("cp.async.wait_group 1;" ::: "memory");
        __syncthreads();   // also guarantees all warps done computing c-1

        const uint32_t aT = sb + (uint32_t)s * STGB;
        const uint32_t bT = sb + 3 * STGB + (uint32_t)s * STGB;

        #pragma unroll
        for (int ks = 0; ks < 4; ++ks) {
            uint32_t a[4][4], bq[2][4];
            #pragma unroll
            for (int mt = 0; mt < 4; ++mt)
                ldsm_x4(a[mt], aT + (offA[mt] ^ (ks << 5)));
            #pragma unroll
            for (int nt = 0; nt < 2; ++nt)
                ldsm_x4(bq[nt], bT + (offB[nt] ^ (ks << 5)));
            #pragma unroll
            for (int mt = 0; mt < 4; ++mt) {
                #pragma unroll
                for (int nt = 0; nt < 2; ++nt) {
                    mma16816(acc[mt][nt * 2 + 0], a[mt], bq[nt][0], bq[nt][2]);
                    mma16816(acc[mt][nt * 2 + 1], a[mt], bq[nt][1], bq[nt][3]);
                }
            }
        }

        if (c + 2 < NCH) load_chunk(c + 2, s2);
        s  = (s  == 2) ? 0 : s + 1;
        s2 = (s2 == 2) ? 0 : s2 + 1;
    }

    // Epilogue: lane l -> row g=l>>2 (+8), cols 2*(l&3) within each n8 frag
    const int g  = lane >> 2;
    const int tg = (lane & 3) * 2;
    #pragma unroll
    for (int mt = 0; mt < 4; ++mt) {
        const int r0 = rowBase + wm + mt * 16 + g;
        const float xs0 = g_xsq[r0];
        const float xs1 = g_xsq[r0 + 8];
        float* p0 = C + (size_t)r0 * ND + colBase + wn;
        float* p1 = p0 + (size_t)8 * ND;
        #pragma unroll
        for (int nf = 0; nf < 4; ++nf) {
            const int col = nf * 8 + tg;
            const float w0 = wsq_s[wn + col];
            const float w1 = wsq_s[wn + col + 1];
            float2 v0, v1;
            v0.x = xs0 + w0 - 2.f * acc[mt][nf][0];
            v0.y = xs0 + w1 - 2.f * acc[mt][nf][1];
            v1.x = xs1 + w0 - 2.f * acc[mt][nf][2];
            v1.y = xs1 + w1 - 2.f * acc[mt][nf][3];
            *reinterpret_cast<float2*>(p0 + col) = v0;
            *reinterpret_cast<float2*>(p1 + col) = v1;
        }
    }
}

// ---------------------------------------------------------------------------
extern "C" void kernel_launch(void* const* d_in, const int* in_sizes, int n_in,
                              void* d_out, int out_size) {
    const float* x = (const float*)d_in[0];
    const float* w = (const float*)d_in[1];
    float* out = (float*)d_out;

    prep_kernel<<<1024 + 512, 256>>>(x, w);

    cudaFuncSetAttribute(rbf_mma_gemm,
                         cudaFuncAttributeMaxDynamicSharedMemorySize, SMEM_BYTES);
    rbf_mma_gemm<<<dim3(ND / 128, MB / 128), 256, SMEM_BYTES>>>(out);
}

// round 16
// speedup vs baseline: 1.5704x; 1.0074x over previous
#include <cuda_runtime.h>
#include <cuda_bf16.h>
#include <cstdint>

#define MB 8192   // M
#define KD 1024   // K
#define ND 4096   // N

// ---------------- device scratch (no allocs allowed) ----------------
__device__ float g_xsq[MB];
__device__ float g_wsq_part[8][ND];
__device__ __nv_bfloat16 g_xb[(size_t)MB * KD];   // x in bf16, [M][K]
__device__ __nv_bfloat16 g_wb[(size_t)ND * KD];   // W in bf16, TRANSPOSED [N][K]

// ---------------- helpers ----------------
__device__ __forceinline__ uint32_t smem_u32(const void* p) {
    uint32_t a;
    asm("{ .reg .u64 t; cvta.to.shared.u64 t, %1; cvt.u32.u64 %0, t; }"
        : "=r"(a) : "l"(p));
    return a;
}

__device__ __forceinline__ void cp_async16(uint32_t dst, const void* src) {
    asm volatile("cp.async.cg.shared.global [%0], [%1], 16;"
                 :: "r"(dst), "l"(src) : "memory");
}

__device__ __forceinline__ uint32_t swz(uint32_t b) {  // SW128: Swizzle<3,4,3>
    return b ^ ((b >> 3) & 0x70);
}

__device__ __forceinline__ void ldsm_x4(uint32_t* r, uint32_t addr) {
    asm volatile("ldmatrix.sync.aligned.m8n8.x4.shared.b16 {%0,%1,%2,%3}, [%4];"
                 : "=r"(r[0]), "=r"(r[1]), "=r"(r[2]), "=r"(r[3]) : "r"(addr));
}

__device__ __forceinline__ void mma16816(float* d, const uint32_t* a,
                                         uint32_t b0, uint32_t b1) {
    asm volatile(
        "mma.sync.aligned.m16n8k16.row.col.f32.bf16.bf16.f32 "
        "{%0,%1,%2,%3}, {%4,%5,%6,%7}, {%8,%9}, {%0,%1,%2,%3};"
        : "+f"(d[0]), "+f"(d[1]), "+f"(d[2]), "+f"(d[3])
        : "r"(a[0]), "r"(a[1]), "r"(a[2]), "r"(a[3]), "r"(b0), "r"(b1));
}

// ---------------------------------------------------------------------------
// Merged prep kernel, 256 threads/block:
//   blocks [0, 1024):     convert x rows -> bf16 + ||x_b||^2
//   blocks [1024, 2048):  convert W stripe (128-row K slab) -> transposed
//                         bf16 + partial wsq  (8 slabs x 128 stripes)
// Each block takes exactly one branch, so barriers stay block-uniform.
// ---------------------------------------------------------------------------
__global__ void prep_kernel(const float* __restrict__ x,
                            const float* __restrict__ w) {
    const int tid = threadIdx.x;
    if (blockIdx.x < 1024) {
        // ---- convert_x: 8 rows per block, one warp per row ----
        int row  = blockIdx.x * 8 + (tid >> 5);
        int lane = tid & 31;
        const float4* xr = reinterpret_cast<const float4*>(x + (size_t)row * KD);
        uint2* dst = reinterpret_cast<uint2*>(g_xb + (size_t)row * KD);
        float s = 0.f;
        #pragma unroll 8
        for (int i = lane; i < KD / 4; i += 32) {
            float4 v = xr[i];
            s += v.x * v.x + v.y * v.y + v.z * v.z + v.w * v.w;
            __nv_bfloat162 lo = __floats2bfloat162_rn(v.x, v.y);
            __nv_bfloat162 hi = __floats2bfloat162_rn(v.z, v.w);
            uint2 u;
            u.x = *reinterpret_cast<uint32_t*>(&lo);
            u.y = *reinterpret_cast<uint32_t*>(&hi);
            dst[i] = u;
        }
        #pragma unroll
        for (int o = 16; o > 0; o >>= 1) s += __shfl_xor_sync(0xffffffffu, s, o);
        if (lane == 0) g_xsq[row] = s;
    } else {
        // ---- convert_w: 32-col stripe over a 128-row K slab ----
        __shared__ __nv_bfloat16 t[64][34];
        __shared__ float red[8][32];
        const int bid   = blockIdx.x - 1024;
        const int n0    = (bid & 127) * 32;     // ND/32 = 128 stripes
        const int kbase = (bid >> 7) * 128;     // 8 K slabs of 128 rows
        const int c   = tid & 31, r0 = tid >> 5;
        const int n   = tid >> 3, seg = (tid & 7) * 8;

        float sq = 0.f;
        for (int k0 = kbase; k0 < kbase + 128; k0 += 64) {
            #pragma unroll
            for (int p = 0; p < 8; ++p) {
                int r = p * 8 + r0;
                float v = w[(size_t)(k0 + r) * ND + n0 + c];
                sq += v * v;
                t[r][c] = __float2bfloat16_rn(v);
            }
            __syncthreads();
            __nv_bfloat16 tmp[8];
            #pragma unroll
            for (int i = 0; i < 8; ++i) tmp[i] = t[seg + i][n];
            *reinterpret_cast<uint4*>(g_wb + (size_t)(n0 + n) * KD + k0 + seg) =
                *reinterpret_cast<uint4*>(tmp);
            __syncthreads();
        }
        red[r0][c] = sq;
        __syncthreads();
        if (tid < 32) {
            float s = 0.f;
            #pragma unroll
            for (int p = 0; p < 8; ++p) s += red[p][tid];
            g_wsq_part[bid >> 7][n0 + tid] = s;
        }
    }
}

// ---------------------------------------------------------------------------
// mma.sync bf16 GEMM + fused epilogue  (R8 mainloop — proven 188.8us):
//   C[m,n] = xsq[m] + wsq[n] - 2 * (x @ W)[m,n]
// wsq partials (8) summed into a 512B smem stage before the mainloop
// (made visible to the epilogue by the mainloop barriers).
// ---------------------------------------------------------------------------
#define KC 64
#define NCH (KD / KC)          // 16
#define STGB 16384             // bytes per operand per stage
#define SMEM_BYTES (6 * STGB + 512)  // 96 KB tiles + wsq stage

__global__ __launch_bounds__(256, 2)
void rbf_mma_gemm(float* __restrict__ C) {
    extern __shared__ __align__(1024) char smem[];
    const uint32_t sb = smem_u32(smem);
    float* wsq_s = reinterpret_cast<float*>(smem + 6 * STGB);

    const int tid  = threadIdx.x;
    const int lane = tid & 31;
    const int wid  = tid >> 5;
    const int wm   = (wid & 1) * 64;    // warp M offset
    const int wn   = (wid >> 1) * 32;   // warp N offset
    const int rowBase = blockIdx.y * 128;
    const int colBase = blockIdx.x * 128;

    // cp.async geometry: 256 threads x 4 rows x 16B per operand tile
    const int lr  = tid >> 3;          // 0..31
    const int seg = (tid & 7) * 16;    // byte 0..112

    auto load_chunk = [&](int c, int s) {
        const uint32_t aT = sb + (uint32_t)s * STGB;
        const uint32_t bT = sb + 3 * STGB + (uint32_t)s * STGB;
        const size_t k0 = (size_t)c * KC;
        #pragma unroll
        for (int p = 0; p < 4; ++p) {
            int r = p * 32 + lr;
            cp_async16(aT + swz(r * 128 + seg),
                       (const char*)(g_xb + (size_t)(rowBase + r) * KD + k0) + seg);
            cp_async16(bT + swz(r * 128 + seg),
                       (const char*)(g_wb + (size_t)(colBase + r) * KD + k0) + seg);
        }
        asm volatile("cp.async.commit_group;" ::: "memory");
    };

    load_chunk(0, 0);
    load_chunk(1, 1);

    // Fold wsq partial reduction into this kernel (replaces reduce launch).
    // Visible to the epilogue via the mainloop __syncthreads.
    if (tid < 128) {
        int col = colBase + tid;
        wsq_s[tid] = ((g_wsq_part[0][col] + g_wsq_part[1][col]) +
                      (g_wsq_part[2][col] + g_wsq_part[3][col])) +
                     ((g_wsq_part[4][col] + g_wsq_part[5][col]) +
                      (g_wsq_part[6][col] + g_wsq_part[7][col]));
    }

    // ldmatrix base offsets (swizzled once; ks advances via XOR of ks*32,
    // valid because the SW128 mask depends only on bits 7-9 = row bits)
    const int rl = lane & 15;
    const int hi = (lane >> 4) * 16;
    uint32_t offA[4], offB[2];
    #pragma unroll
    for (int mt = 0; mt < 4; ++mt)
        offA[mt] = swz((uint32_t)(wm + mt * 16 + rl) * 128 + hi);
    #pragma unroll
    for (int nt = 0; nt < 2; ++nt)
        offB[nt] = swz((uint32_t)(wn + nt * 16 + rl) * 128 + hi);

    float acc[4][4][4];
    #pragma unroll
    for (int i = 0; i < 4; ++i)
        #pragma unroll
        for (int j = 0; j < 4; ++j)
            #pragma unroll
            for (int k = 0; k < 4; ++k) acc[i][j][k] = 0.f;

    int s = 0, s2 = 2;   // stage of chunk c, stage for chunk c+2
    for (int c = 0; c < NCH; ++c) {
        asm volatile("cp.async.wait_group 1;" ::: "memory");
        __syncthreads();   // also guarantees all warps done computing c-1

        const uint32_t aT = sb + (uint32_t)s * STGB;
        const uint32_t bT = sb + 3 * STGB + (uint32_t)s * STGB;

        #pragma unroll
        for (int ks = 0; ks < 4; ++ks) {
            uint32_t a[4][4], bq[2][4];
            #pragma unroll
            for (int mt = 0; mt < 4; ++mt)
                ldsm_x4(a[mt], aT + (offA[mt] ^ (ks << 5)));
            #pragma unroll
            for (int nt = 0; nt < 2; ++nt)
                ldsm_x4(bq[nt], bT + (offB[nt] ^ (ks << 5)));
            #pragma unroll
            for (int mt = 0; mt < 4; ++mt) {
                #pragma unroll
                for (int nt = 0; nt < 2; ++nt) {
                    mma16816(acc[mt][nt * 2 + 0], a[mt], bq[nt][0], bq[nt][2]);
                    mma16816(acc[mt][nt * 2 + 1], a[mt], bq[nt][1], bq[nt][3]);
                }
            }
        }

        if (c + 2 < NCH) load_chunk(c + 2, s2);
        s  = (s  == 2) ? 0 : s + 1;
        s2 = (s2 == 2) ? 0 : s2 + 1;
    }

    // Epilogue: lane l -> row g=l>>2 (+8), cols 2*(l&3) within each n8 frag
    const int g  = lane >> 2;
    const int tg = (lane & 3) * 2;
    #pragma unroll
    for (int mt = 0; mt < 4; ++mt) {
        const int r0 = rowBase + wm + mt * 16 + g;
        const float xs0 = g_xsq[r0];
        const float xs1 = g_xsq[r0 + 8];
        float* p0 = C + (size_t)r0 * ND + colBase + wn;
        float* p1 = p0 + (size_t)8 * ND;
        #pragma unroll
        for (int nf = 0; nf < 4; ++nf) {
            const int col = nf * 8 + tg;
            const float w0 = wsq_s[wn + col];
            const float w1 = wsq_s[wn + col + 1];
            float2 v0, v1;
            v0.x = xs0 + w0 - 2.f * acc[mt][nf][0];
            v0.y = xs0 + w1 - 2.f * acc[mt][nf][1];
            v1.x = xs1 + w0 - 2.f * acc[mt][nf][2];
            v1.y = xs1 + w1 - 2.f * acc[mt][nf][3];
            *reinterpret_cast<float2*>(p0 + col) = v0;
            *reinterpret_cast<float2*>(p1 + col) = v1;
        }
    }
}

// ---------------------------------------------------------------------------
extern "C" void kernel_launch(void* const* d_in, const int* in_sizes, int n_in,
                              void* d_out, int out_size) {
    const float* x = (const float*)d_in[0];
    const float* w = (const float*)d_in[1];
    float* out = (float*)d_out;

    prep_kernel<<<2048, 256>>>(x, w);

    cudaFuncSetAttribute(rbf_mma_gemm,
                         cudaFuncAttributeMaxDynamicSharedMemorySize, SMEM_BYTES);
    rbf_mma_gemm<<<dim3(ND / 128, MB / 128), 256, SMEM_BYTES>>>(out);
}

// round 17
// speedup vs baseline: 1.5746x; 1.0027x over previous
#include <cuda_runtime.h>
#include <cuda_bf16.h>
#include <cstdint>

#define MB 8192   // M
#define KD 1024   // K
#define ND 4096   // N

// ---------------- device scratch (no allocs allowed) ----------------
__device__ float g_xsq[MB];
__device__ float g_wsq_part[8][ND];
__device__ __nv_bfloat16 g_xb[(size_t)MB * KD];   // x in bf16, [M][K]
__device__ __nv_bfloat16 g_wb[(size_t)ND * KD];   // W in bf16, TRANSPOSED [N][K]

// ---------------- helpers ----------------
__device__ __forceinline__ uint32_t smem_u32(const void* p) {
    uint32_t a;
    asm("{ .reg .u64 t; cvta.to.shared.u64 t, %1; cvt.u32.u64 %0, t; }"
        : "=r"(a) : "l"(p));
    return a;
}

__device__ __forceinline__ void cp_async16(uint32_t dst, const void* src) {
    asm volatile("cp.async.cg.shared.global [%0], [%1], 16;"
                 :: "r"(dst), "l"(src) : "memory");
}

__device__ __forceinline__ uint32_t swz(uint32_t b) {  // SW128: Swizzle<3,4,3>
    return b ^ ((b >> 3) & 0x70);
}

__device__ __forceinline__ void ldsm_x4(uint32_t* r, uint32_t addr) {
    asm volatile("ldmatrix.sync.aligned.m8n8.x4.shared.b16 {%0,%1,%2,%3}, [%4];"
                 : "=r"(r[0]), "=r"(r[1]), "=r"(r[2]), "=r"(r[3]) : "r"(addr));
}

__device__ __forceinline__ void mma16816(float* d, const uint32_t* a,
                                         uint32_t b0, uint32_t b1) {
    asm volatile(
        "mma.sync.aligned.m16n8k16.row.col.f32.bf16.bf16.f32 "
        "{%0,%1,%2,%3}, {%4,%5,%6,%7}, {%8,%9}, {%0,%1,%2,%3};"
        : "+f"(d[0]), "+f"(d[1]), "+f"(d[2]), "+f"(d[3])
        : "r"(a[0]), "r"(a[1]), "r"(a[2]), "r"(a[3]), "r"(b0), "r"(b1));
}

__device__ __forceinline__ uint32_t pack2(float a, float b) {
    __nv_bfloat162 h = __floats2bfloat162_rn(a, b);
    return *reinterpret_cast<uint32_t*>(&h);
}

// ---------------------------------------------------------------------------
// Merged prep kernel, 256 threads/block:
//   blocks [0, 1024):     convert x rows -> bf16 + ||x_b||^2 (16B stores)
//   blocks [1024, 2048):  convert W stripe (128-row K slab) -> transposed
//                         bf16 + partial wsq  (8 slabs x 128 stripes)
// Each block takes exactly one branch, so barriers stay block-uniform.
// ---------------------------------------------------------------------------
__global__ void prep_kernel(const float* __restrict__ x,
                            const float* __restrict__ w) {
    const int tid = threadIdx.x;
    if (blockIdx.x < 1024) {
        // ---- convert_x: 8 rows per block, one warp per row.
        //      Lane owns 8 consecutive floats per iter -> one STG.128.
        int row  = blockIdx.x * 8 + (tid >> 5);
        int lane = tid & 31;
        const float4* xr = reinterpret_cast<const float4*>(x + (size_t)row * KD);
        uint4* dst = reinterpret_cast<uint4*>(g_xb + (size_t)row * KD);
        float s = 0.f;
        #pragma unroll
        for (int i = 0; i < 4; ++i) {
            int idx = i * 32 + lane;            // 8-float segment index (0..127)
            float4 v0 = xr[idx * 2];
            float4 v1 = xr[idx * 2 + 1];
            s += v0.x * v0.x + v0.y * v0.y + v0.z * v0.z + v0.w * v0.w;
            s += v1.x * v1.x + v1.y * v1.y + v1.z * v1.z + v1.w * v1.w;
            uint4 u;
            u.x = pack2(v0.x, v0.y);
            u.y = pack2(v0.z, v0.w);
            u.z = pack2(v1.x, v1.y);
            u.w = pack2(v1.z, v1.w);
            dst[idx] = u;
        }
        #pragma unroll
        for (int o = 16; o > 0; o >>= 1) s += __shfl_xor_sync(0xffffffffu, s, o);
        if (lane == 0) g_xsq[row] = s;
    } else {
        // ---- convert_w: 32-col stripe over a 128-row K slab ----
        __shared__ __nv_bfloat16 t[64][34];
        __shared__ float red[8][32];
        const int bid   = blockIdx.x - 1024;
        const int n0    = (bid & 127) * 32;     // ND/32 = 128 stripes
        const int kbase = (bid >> 7) * 128;     // 8 K slabs of 128 rows
        const int c   = tid & 31, r0 = tid >> 5;
        const int n   = tid >> 3, seg = (tid & 7) * 8;

        float sq = 0.f;
        for (int k0 = kbase; k0 < kbase + 128; k0 += 64) {
            #pragma unroll
            for (int p = 0; p < 8; ++p) {
                int r = p * 8 + r0;
                float v = w[(size_t)(k0 + r) * ND + n0 + c];
                sq += v * v;
                t[r][c] = __float2bfloat16_rn(v);
            }
            __syncthreads();
            __nv_bfloat16 tmp[8];
            #pragma unroll
            for (int i = 0; i < 8; ++i) tmp[i] = t[seg + i][n];
            *reinterpret_cast<uint4*>(g_wb + (size_t)(n0 + n) * KD + k0 + seg) =
                *reinterpret_cast<uint4*>(tmp);
            __syncthreads();
        }
        red[r0][c] = sq;
        __syncthreads();
        if (tid < 32) {
            float s = 0.f;
            #pragma unroll
            for (int p = 0; p < 8; ++p) s += red[p][tid];
            g_wsq_part[bid >> 7][n0 + tid] = s;
        }
    }
}

// ---------------------------------------------------------------------------
// mma.sync bf16 GEMM + fused epilogue  (R8 mainloop — proven 188.8us):
//   C[m,n] = xsq[m] + wsq[n] - 2 * (x @ W)[m,n]
// wsq partials (8) summed into a 512B smem stage before the mainloop
// (made visible to the epilogue by the mainloop barriers).
// ---------------------------------------------------------------------------
#define KC 64
#define NCH (KD / KC)          // 16
#define STGB 16384             // bytes per operand per stage
#define SMEM_BYTES (6 * STGB + 512)  // 96 KB tiles + wsq stage

__global__ __launch_bounds__(256, 2)
void rbf_mma_gemm(float* __restrict__ C) {
    extern __shared__ __align__(1024) char smem[];
    const uint32_t sb = smem_u32(smem);
    float* wsq_s = reinterpret_cast<float*>(smem + 6 * STGB);

    const int tid  = threadIdx.x;
    const int lane = tid & 31;
    const int wid  = tid >> 5;
    const int wm   = (wid & 1) * 64;    // warp M offset
    const int wn   = (wid >> 1) * 32;   // warp N offset
    const int rowBase = blockIdx.y * 128;
    const int colBase = blockIdx.x * 128;

    // cp.async geometry: 256 threads x 4 rows x 16B per operand tile
    const int lr  = tid >> 3;          // 0..31
    const int seg = (tid & 7) * 16;    // byte 0..112

    auto load_chunk = [&](int c, int s) {
        const uint32_t aT = sb + (uint32_t)s * STGB;
        const uint32_t bT = sb + 3 * STGB + (uint32_t)s * STGB;
        const size_t k0 = (size_t)c * KC;
        #pragma unroll
        for (int p = 0; p < 4; ++p) {
            int r = p * 32 + lr;
            cp_async16(aT + swz(r * 128 + seg),
                       (const char*)(g_xb + (size_t)(rowBase + r) * KD + k0) + seg);
            cp_async16(bT + swz(r * 128 + seg),
                       (const char*)(g_wb + (size_t)(colBase + r) * KD + k0) + seg);
        }
        asm volatile("cp.async.commit_group;" ::: "memory");
    };

    load_chunk(0, 0);
    load_chunk(1, 1);

    // Fold wsq partial reduction into this kernel (replaces reduce launch).
    // Visible to the epilogue via the mainloop __syncthreads.
    if (tid < 128) {
        int col = colBase + tid;
        wsq_s[tid] = ((g_wsq_part[0][col] + g_wsq_part[1][col]) +
                      (g_wsq_part[2][col] + g_wsq_part[3][col])) +
                     ((g_wsq_part[4][col] + g_wsq_part[5][col]) +
                      (g_wsq_part[6][col] + g_wsq_part[7][col]));
    }

    // ldmatrix base offsets (swizzled once; ks advances via XOR of ks*32,
    // valid because the SW128 mask depends only on bits 7-9 = row bits)
    const int rl = lane & 15;
    const int hi = (lane >> 4) * 16;
    uint32_t offA[4], offB[2];
    #pragma unroll
    for (int mt = 0; mt < 4; ++mt)
        offA[mt] = swz((uint32_t)(wm + mt * 16 + rl) * 128 + hi);
    #pragma unroll
    for (int nt = 0; nt < 2; ++nt)
        offB[nt] = swz((uint32_t)(wn + nt * 16 + rl) * 128 + hi);

    float acc[4][4][4];
    #pragma unroll
    for (int i = 0; i < 4; ++i)
        #pragma unroll
        for (int j = 0; j < 4; ++j)
            #pragma unroll
            for (int k = 0; k < 4; ++k) acc[i][j][k] = 0.f;

    int s = 0, s2 = 2;   // stage of chunk c, stage for chunk c+2
    for (int c = 0; c < NCH; ++c) {
        asm volatile("cp.async.wait_group 1;" ::: "memory");
        __syncthreads();   // also guarantees all warps done computing c-1

        const uint32_t aT = sb + (uint32_t)s * STGB;
        const uint32_t bT = sb + 3 * STGB + (uint32_t)s * STGB;

        #pragma unroll
        for (int ks = 0; ks < 4; ++ks) {
            uint32_t a[4][4], bq[2][4];
            #pragma unroll
            for (int mt = 0; mt < 4; ++mt)
                ldsm_x4(a[mt], aT + (offA[mt] ^ (ks << 5)));
            #pragma unroll
            for (int nt = 0; nt < 2; ++nt)
                ldsm_x4(bq[nt], bT + (offB[nt] ^ (ks << 5)));
            #pragma unroll
            for (int mt = 0; mt < 4; ++mt) {
                #pragma unroll
                for (int nt = 0; nt < 2; ++nt) {
                    mma16816(acc[mt][nt * 2 + 0], a[mt], bq[nt][0], bq[nt][2]);
                    mma16816(acc[mt][nt * 2 + 1], a[mt], bq[nt][1], bq[nt][3]);
                }
            }
        }

        if (c + 2 < NCH) load_chunk(c + 2, s2);
        s  = (s  == 2) ? 0 : s + 1;
        s2 = (s2 == 2) ? 0 : s2 + 1;
    }

    // Epilogue: lane l -> row g=l>>2 (+8), cols 2*(l&3) within each n8 frag
    const int g  = lane >> 2;
    const int tg = (lane & 3) * 2;
    #pragma unroll
    for (int mt = 0; mt < 4; ++mt) {
        const int r0 = rowBase + wm + mt * 16 + g;
        const float xs0 = g_xsq[r0];
        const float xs1 = g_xsq[r0 + 8];
        float* p0 = C + (size_t)r0 * ND + colBase + wn;
        float* p1 = p0 + (size_t)8 * ND;
        #pragma unroll
        for (int nf = 0; nf < 4; ++nf) {
            const int col = nf * 8 + tg;
            const float w0 = wsq_s[wn + col];
            const float w1 = wsq_s[wn + col + 1];
            float2 v0, v1;
            v0.x = xs0 + w0 - 2.f * acc[mt][nf][0];
            v0.y = xs0 + w1 - 2.f * acc[mt][nf][1];
            v1.x = xs1 + w0 - 2.f * acc[mt][nf][2];
            v1.y = xs1 + w1 - 2.f * acc[mt][nf][3];
            *reinterpret_cast<float2*>(p0 + col) = v0;
            *reinterpret_cast<float2*>(p1 + col) = v1;
        }
    }
}

// ---------------------------------------------------------------------------
extern "C" void kernel_launch(void* const* d_in, const int* in_sizes, int n_in,
                              void* d_out, int out_size) {
    const float* x = (const float*)d_in[0];
    const float* w = (const float*)d_in[1];
    float* out = (float*)d_out;

    prep_kernel<<<2048, 256>>>(x, w);

    cudaFuncSetAttribute(rbf_mma_gemm,
                         cudaFuncAttributeMaxDynamicSharedMemorySize, SMEM_BYTES);
    rbf_mma_gemm<<<dim3(ND / 128, MB / 128), 256, SMEM_BYTES>>>(out);
}